// round 14
// baseline (speedup 1.0000x reference)
#include <cuda_runtime.h>
#include <cuda_fp16.h>

#define D_MODEL 768
#define SEQ     2048
#define BATCH   2
#define NHEAD   12
#define DK      64
#define MTOT    (BATCH*SEQ)   /* 4096 */
#define NIN     (MTOT*D_MODEL)
#define NW      (D_MODEL*D_MODEL)
#define NSPLIT  2
#define KSPAN   (SEQ / NSPLIT)   /* 1024 keys per split */

// fp16 copies of inputs + intermediates (no cudaMalloc allowed)
__device__ __half g_qin[NIN], g_kin[NIN], g_vin[NIN];
__device__ __half g_wq[NW], g_wk[NW], g_wv[NW], g_wo[NW];
__device__ __half g_Qh[NIN], g_Kh[NIN], g_Vh[NIN], g_ctxh[NIN];
// split-KV partials (fp32: p<=2^9, l<=2^19 -> must not be fp16)
__device__ float  g_po[NSPLIT * NIN];
__device__ float  g_pl[NSPLIT * MTOT * NHEAD];

extern __shared__ unsigned char dynsm[];

// ---------------------------------------------------------------------------
// helpers
// ---------------------------------------------------------------------------
__device__ __forceinline__ void mma16(float d[4], const unsigned a[4], const unsigned b[2]) {
    asm volatile(
        "mma.sync.aligned.m16n8k16.row.col.f32.f16.f16.f32 "
        "{%0,%1,%2,%3},{%4,%5,%6,%7},{%8,%9},{%0,%1,%2,%3};"
        : "+f"(d[0]), "+f"(d[1]), "+f"(d[2]), "+f"(d[3])
        : "r"(a[0]), "r"(a[1]), "r"(a[2]), "r"(a[3]),
          "r"(b[0]), "r"(b[1]));
}
__device__ __forceinline__ unsigned ld32(const __half* p) {
    return *(const unsigned*)p;
}
__device__ __forceinline__ unsigned h2u(float x, float y) {
    __half2 h = __floats2half2_rn(x, y);
    return *(unsigned*)&h;
}
__device__ __forceinline__ float ex2(float x) {
    float r;
    asm("ex2.approx.f32 %0, %1;" : "=f"(r) : "f"(x));
    return r;
}
__device__ __forceinline__ void cp16(void* dst, const void* src) {
    unsigned d = (unsigned)__cvta_generic_to_shared(dst);
    asm volatile("cp.async.cg.shared.global [%0], [%1], 16;\n" :: "r"(d), "l"(src));
}
__device__ __forceinline__ void cp_commit() {
    asm volatile("cp.async.commit_group;\n" ::: "memory");
}
template <int N>
__device__ __forceinline__ void cp_wait() {
    asm volatile("cp.async.wait_group %0;\n" :: "n"(N) : "memory");
}
__device__ __forceinline__ void ldm_x4(unsigned& r0, unsigned& r1,
                                       unsigned& r2, unsigned& r3, const __half* p) {
    unsigned a = (unsigned)__cvta_generic_to_shared(p);
    asm volatile("ldmatrix.sync.aligned.m8n8.x4.shared.b16 {%0,%1,%2,%3}, [%4];"
                 : "=r"(r0), "=r"(r1), "=r"(r2), "=r"(r3) : "r"(a));
}
__device__ __forceinline__ void ldm_x4_t(unsigned& r0, unsigned& r1,
                                         unsigned& r2, unsigned& r3, const __half* p) {
    unsigned a = (unsigned)__cvta_generic_to_shared(p);
    asm volatile("ldmatrix.sync.aligned.m8n8.x4.trans.shared.b16 {%0,%1,%2,%3}, [%4];"
                 : "=r"(r0), "=r"(r1), "=r"(r2), "=r"(r3) : "r"(a));
}

#define LOG2E 1.4426950408889634f

// ---------------------------------------------------------------------------
// fp32 -> fp16 conversion pre-pass (7 arrays via blockIdx.y)
// ---------------------------------------------------------------------------
__global__ void __launch_bounds__(256)
cvt_kernel(const float* q, const float* k, const float* v,
           const float* wq, const float* wk, const float* wv, const float* wo)
{
    const int y = blockIdx.y;
    const float* src;
    __half* dst;
    int n;
    switch (y) {
        case 0: src = q;  dst = g_qin; n = NIN; break;
        case 1: src = k;  dst = g_kin; n = NIN; break;
        case 2: src = v;  dst = g_vin; n = NIN; break;
        case 3: src = wq; dst = g_wq;  n = NW;  break;
        case 4: src = wk; dst = g_wk;  n = NW;  break;
        case 5: src = wv; dst = g_wv;  n = NW;  break;
        default: src = wo; dst = g_wo; n = NW;  break;
    }
    int i = (blockIdx.x * 256 + threadIdx.x) * 4;
    if (i >= n) return;
    float4 f = *(const float4*)(src + i);
    __half2* d2 = (__half2*)(dst + i);
    d2[0] = __floats2half2_rn(f.x, f.y);
    d2[1] = __floats2half2_rn(f.z, f.w);
}

// ---------------------------------------------------------------------------
// fp16 GEMM (R13, frozen): tile 64x128x32, 128 threads, occ 4, ldmatrix.
// ---------------------------------------------------------------------------
#define HPAD 40
#define ABUF (64 * HPAD)
#define WBUF (128 * HPAD)
#define GEMM_SMEM_BYTES (3 * (ABUF + WBUF) * 2)   /* 46080 B */

__device__ __forceinline__ void gemm_stage(__half* Ad, __half* Wd,
                                           const __half* __restrict__ A,
                                           const __half* __restrict__ W,
                                           int bm, int bn, int k0, int tid)
{
#pragma unroll
    for (int u = 0; u < 2; u++) {
        int idx = tid + (u << 7);
        int r = idx >> 2;
        int c = (idx & 3) << 3;
        cp16(&Ad[r * HPAD + c], A + (size_t)(bm + r) * D_MODEL + k0 + c);
    }
#pragma unroll
    for (int u = 0; u < 4; u++) {
        int idx = tid + (u << 7);
        int r = idx >> 2;
        int c = (idx & 3) << 3;
        cp16(&Wd[r * HPAD + c], W + (size_t)(bn + r) * D_MODEL + k0 + c);
    }
    cp_commit();
}

__device__ __forceinline__ void gemm_fp16(const __half* __restrict__ A,
                                          const __half* __restrict__ W,
                                          __half* __restrict__ Ch,
                                          float* __restrict__ Cf,
                                          float scale)
{
    __half* As = (__half*)dynsm;
    __half* Ws = (__half*)dynsm + 3 * ABUF;

    const int tid  = threadIdx.x;
    const int lane = tid & 31;
    const int warp = tid >> 5;
    const int wm   = (warp & 1) * 32;
    const int wn   = (warp >> 1) * 64;
    const int bm   = blockIdx.y * 64;
    const int bn   = blockIdx.x * 128;

    const int a_row = (lane & 15);
    const int a_kof = (lane >> 4) << 3;
    const int b_row = (lane & 7) + ((lane & 16) >> 1);
    const int b_kof = (lane & 8);

    float acc[2][8][4];
#pragma unroll
    for (int mi = 0; mi < 2; mi++)
#pragma unroll
        for (int ni = 0; ni < 8; ni++)
#pragma unroll
            for (int r = 0; r < 4; r++) acc[mi][ni][r] = 0.0f;

    gemm_stage(As, Ws, A, W, bm, bn, 0, tid);
    gemm_stage(As + ABUF, Ws + WBUF, A, W, bm, bn, 32, tid);

    const int NT = D_MODEL / 32;   // 24
    for (int t = 0; t < NT; t++) {
        if (t + 2 < NT) {
            int s2 = (t + 2) % 3;
            gemm_stage(As + s2 * ABUF, Ws + s2 * WBUF, A, W, bm, bn, (t + 2) * 32, tid);
        }
        cp_wait<2>();
        __syncthreads();

        const __half* Ab = As + (t % 3) * ABUF;
        const __half* Wb = Ws + (t % 3) * WBUF;

#pragma unroll
        for (int ks = 0; ks < 2; ks++) {
            const int kc = ks << 4;
            unsigned a[2][4], b[8][2];
#pragma unroll
            for (int mi = 0; mi < 2; mi++)
                ldm_x4(a[mi][0], a[mi][1], a[mi][2], a[mi][3],
                       Ab + (wm + (mi << 4) + a_row) * HPAD + kc + a_kof);
#pragma unroll
            for (int np = 0; np < 4; np++)
                ldm_x4(b[2 * np][0], b[2 * np][1], b[2 * np + 1][0], b[2 * np + 1][1],
                       Wb + (wn + (np << 4) + b_row) * HPAD + kc + b_kof);
#pragma unroll
            for (int mi = 0; mi < 2; mi++)
#pragma unroll
                for (int ni = 0; ni < 8; ni++)
                    mma16(acc[mi][ni], a[mi], b[ni]);
        }
        __syncthreads();
    }

#pragma unroll
    for (int mi = 0; mi < 2; mi++) {
#pragma unroll
        for (int ni = 0; ni < 8; ni++) {
            int row = bm + wm + (mi << 4) + (lane >> 2);
            int col = bn + wn + (ni << 3) + ((lane & 3) << 1);
            if (Ch) {
                *(__half2*)(Ch + (size_t)row * D_MODEL + col) =
                    __floats2half2_rn(acc[mi][ni][0] * scale, acc[mi][ni][1] * scale);
                *(__half2*)(Ch + (size_t)(row + 8) * D_MODEL + col) =
                    __floats2half2_rn(acc[mi][ni][2] * scale, acc[mi][ni][3] * scale);
            } else {
                *(float2*)(Cf + (size_t)row * D_MODEL + col) =
                    make_float2(acc[mi][ni][0], acc[mi][ni][1]);
                *(float2*)(Cf + (size_t)(row + 8) * D_MODEL + col) =
                    make_float2(acc[mi][ni][2], acc[mi][ni][3]);
            }
        }
    }
}

__global__ void __launch_bounds__(128, 4)
qkv_proj_kernel()
{
    const int z = blockIdx.z;
    const __half* A = (z == 0) ? g_qin : (z == 1) ? g_kin : g_vin;
    const __half* W = (z == 0) ? g_wq  : (z == 1) ? g_wk  : g_wv;
    __half*       C = (z == 0) ? g_Qh  : (z == 1) ? g_Kh  : g_Vh;
    float scale = (z == 0) ? 0.125f * LOG2E : 1.0f;
    gemm_fp16(A, W, C, nullptr, scale);
}

__global__ void __launch_bounds__(128, 4)
oproj_kernel(float* __restrict__ out)
{
    gemm_fp16(g_ctxh, g_wo, nullptr, out, 1.0f);
}

// ---------------------------------------------------------------------------
// fp16 flash attention, split-KV=2: grid.z selects the 1024-key half.
// NO-MAX base-2 softmax -> partials combine by plain addition.
// Writes UNNORMALIZED fp32 (o, l) partials to scratch.
// ---------------------------------------------------------------------------
#define ATP 72
#define KVBUF (64 * ATP)
#define ATTN_SMEM_BYTES (4 * KVBUF * 2)   /* 36864 B */

__device__ __forceinline__ void attn_stage(__half* Kd, __half* Vd,
                                           const __half* __restrict__ Kg,
                                           const __half* __restrict__ Vg,
                                           int kt, int tid)
{
#pragma unroll
    for (int u = 0; u < 4; u++) {
        int idx = tid + (u << 7);
        int r = idx >> 3;
        int c = (idx & 7) << 3;
        cp16(&Kd[r * ATP + c], Kg + (size_t)(kt + r) * D_MODEL + c);
        cp16(&Vd[r * ATP + c], Vg + (size_t)(kt + r) * D_MODEL + c);
    }
    cp_commit();
}

__global__ void __launch_bounds__(128, 2)
attn_kernel()
{
    const int tid  = threadIdx.x;
    const int lane = tid & 31;
    const int warp = tid >> 5;
    const int bh   = blockIdx.y;
    const int b    = bh / NHEAD;
    const int h    = bh % NHEAD;
    const int q0   = blockIdx.x * 128;
    const int z    = blockIdx.z;

    __half* Ks = (__half*)dynsm;
    __half* Vs = Ks + 2 * KVBUF;

    const __half* Qg = g_Qh + (size_t)(b * SEQ + q0) * D_MODEL + h * DK;
    const __half* Kg = g_Kh + (size_t)(b * SEQ + z * KSPAN) * D_MODEL + h * DK;
    const __half* Vg = g_Vh + (size_t)(b * SEQ + z * KSPAN) * D_MODEL + h * DK;

    attn_stage(Ks, Vs, Kg, Vg, 0, tid);

    const int wrow = warp << 5;
    unsigned q[2][4][4];
#pragma unroll
    for (int mi = 0; mi < 2; mi++) {
#pragma unroll
        for (int ks = 0; ks < 4; ks++) {
            const __half* qp = Qg + (size_t)(wrow + (mi << 4) + (lane >> 2)) * D_MODEL
                                  + (ks << 4) + ((lane & 3) << 1);
            q[mi][ks][0] = ld32(qp);
            q[mi][ks][1] = ld32(qp + 8 * D_MODEL);
            q[mi][ks][2] = ld32(qp + 8);
            q[mi][ks][3] = ld32(qp + 8 * D_MODEL + 8);
        }
    }

    const unsigned bone = (lane < 4) ? 0x3C003C00u : 0u;
    unsigned b_ones[2] = {bone, bone};

    const int b_row = (lane & 7) + ((lane & 16) >> 1);
    const int b_kof = (lane & 8);

    float o[2][8][4];
    float ol[2][4];
#pragma unroll
    for (int mi = 0; mi < 2; mi++) {
#pragma unroll
        for (int nt = 0; nt < 8; nt++)
#pragma unroll
            for (int r = 0; r < 4; r++) o[mi][nt][r] = 0.0f;
#pragma unroll
        for (int r = 0; r < 4; r++) ol[mi][r] = 0.0f;
    }

    const int NT = KSPAN / 64;   // 16

    for (int t = 0; t < NT; t++) {
        if (t + 1 < NT)
            attn_stage(Ks + ((t + 1) & 1) * KVBUF, Vs + ((t + 1) & 1) * KVBUF,
                       Kg, Vg, (t + 1) * 64, tid);
        cp_wait<1>();
        __syncthreads();

        const __half* Kb = Ks + (t & 1) * KVBUF;
        const __half* Vb = Vs + (t & 1) * KVBUF;

        float s[2][8][4];
#pragma unroll
        for (int mi = 0; mi < 2; mi++)
#pragma unroll
            for (int nt = 0; nt < 8; nt++)
#pragma unroll
                for (int r = 0; r < 4; r++) s[mi][nt][r] = 0.0f;

#pragma unroll
        for (int ks = 0; ks < 4; ks++) {
            const int kc = ks << 4;
#pragma unroll
            for (int np = 0; np < 4; np++) {
                unsigned bb[2][2];
                ldm_x4(bb[0][0], bb[0][1], bb[1][0], bb[1][1],
                       Kb + ((np << 4) + b_row) * ATP + kc + b_kof);
                mma16(s[0][2 * np],     q[0][ks], bb[0]);
                mma16(s[1][2 * np],     q[1][ks], bb[0]);
                mma16(s[0][2 * np + 1], q[0][ks], bb[1]);
                mma16(s[1][2 * np + 1], q[1][ks], bb[1]);
            }
        }

#pragma unroll
        for (int mi = 0; mi < 2; mi++)
#pragma unroll
            for (int nt = 0; nt < 8; nt++)
#pragma unroll
                for (int r = 0; r < 4; r++) s[mi][nt][r] = ex2(s[mi][nt][r]);

#pragma unroll
        for (int ks = 0; ks < 4; ks++) {
            unsigned a0[4], a1[4];
            a0[0] = h2u(s[0][2 * ks][0],     s[0][2 * ks][1]);
            a0[1] = h2u(s[0][2 * ks][2],     s[0][2 * ks][3]);
            a0[2] = h2u(s[0][2 * ks + 1][0], s[0][2 * ks + 1][1]);
            a0[3] = h2u(s[0][2 * ks + 1][2], s[0][2 * ks + 1][3]);
            a1[0] = h2u(s[1][2 * ks][0],     s[1][2 * ks][1]);
            a1[1] = h2u(s[1][2 * ks][2],     s[1][2 * ks][3]);
            a1[2] = h2u(s[1][2 * ks + 1][0], s[1][2 * ks + 1][1]);
            a1[3] = h2u(s[1][2 * ks + 1][2], s[1][2 * ks + 1][3]);

            mma16(ol[0], a0, b_ones);
            mma16(ol[1], a1, b_ones);
#pragma unroll
            for (int nt2 = 0; nt2 < 4; nt2++) {
                int row = (ks << 4) + (lane & 15);
                int col = (nt2 << 4) + ((lane & 16) >> 1);
                unsigned r0, r1, r2, r3;
                ldm_x4_t(r0, r1, r2, r3, Vb + row * ATP + col);
                unsigned b0[2] = {r0, r1};
                unsigned b1[2] = {r2, r3};
                mma16(o[0][2 * nt2],     a0, b0);
                mma16(o[1][2 * nt2],     a1, b0);
                mma16(o[0][2 * nt2 + 1], a0, b1);
                mma16(o[1][2 * nt2 + 1], a1, b1);
            }
        }
        __syncthreads();
    }

    // Epilogue: write UNNORMALIZED fp32 partials (o, l)
    float* Po = g_po + (size_t)z * NIN + (size_t)(b * SEQ + q0) * D_MODEL + h * DK;
    float* Pl = g_pl + (size_t)z * MTOT * NHEAD + (size_t)(b * SEQ + q0) * NHEAD + h;
#pragma unroll
    for (int mi = 0; mi < 2; mi++) {
        int row = wrow + (mi << 4) + (lane >> 2);
#pragma unroll
        for (int nt = 0; nt < 8; nt++) {
            int col = (nt << 3) + ((lane & 3) << 1);
            *(float2*)(Po + (size_t)row * D_MODEL + col) =
                make_float2(o[mi][nt][0], o[mi][nt][1]);
            *(float2*)(Po + (size_t)(row + 8) * D_MODEL + col) =
                make_float2(o[mi][nt][2], o[mi][nt][3]);
        }
        if ((lane & 3) == 0) {
            Pl[(size_t)row * NHEAD]       = ol[mi][0];
            Pl[(size_t)(row + 8) * NHEAD] = ol[mi][2];
        }
    }
}

// ---------------------------------------------------------------------------
// split-KV reduce: ctx_fp16 = (o0 + o1) / (l0 + l1)
// ---------------------------------------------------------------------------
__global__ void __launch_bounds__(256)
reduce_kernel()
{
    int i = (blockIdx.x * 256 + threadIdx.x) * 4;
    if (i >= NIN) return;
    int row = i / D_MODEL;
    int col = i % D_MODEL;
    int h   = col >> 6;
    float l = g_pl[row * NHEAD + h] + g_pl[MTOT * NHEAD + row * NHEAD + h];
    float inv = 1.0f / l;
    float4 o0 = *(const float4*)(g_po + i);
    float4 o1 = *(const float4*)(g_po + NIN + i);
    __half2* d2 = (__half2*)(g_ctxh + i);
    d2[0] = __floats2half2_rn((o0.x + o1.x) * inv, (o0.y + o1.y) * inv);
    d2[1] = __floats2half2_rn((o0.z + o1.z) * inv, (o0.w + o1.w) * inv);
}

// ---------------------------------------------------------------------------
extern "C" void kernel_launch(void* const* d_in, const int* in_sizes, int n_in,
                              void* d_out, int out_size)
{
    const float* query  = (const float*)d_in[0];
    const float* key_in = (const float*)d_in[1];
    const float* value  = (const float*)d_in[2];
    const float* Wq     = (const float*)d_in[3];
    const float* Wk     = (const float*)d_in[4];
    const float* Wv     = (const float*)d_in[5];
    const float* Wo     = (const float*)d_in[6];
    float* out = (float*)d_out;

    cudaFuncSetAttribute(attn_kernel,
                         cudaFuncAttributeMaxDynamicSharedMemorySize, ATTN_SMEM_BYTES);
    cudaFuncSetAttribute(qkv_proj_kernel,
                         cudaFuncAttributeMaxDynamicSharedMemorySize, GEMM_SMEM_BYTES);
    cudaFuncSetAttribute(oproj_kernel,
                         cudaFuncAttributeMaxDynamicSharedMemorySize, GEMM_SMEM_BYTES);

    // fp32 -> fp16 pre-pass
    dim3 gcvt((NIN / 4 + 255) / 256, 7);
    cvt_kernel<<<gcvt, 256>>>(query, key_in, value, Wq, Wk, Wv, Wo);

    // Q/K/V projections: 64x128 tiles, 4 CTA/SM
    dim3 gproj(D_MODEL / 128, MTOT / 64, 3);
    qkv_proj_kernel<<<gproj, 128, GEMM_SMEM_BYTES>>>();

    // Flash attention, split-KV=2
    dim3 gattn(SEQ / 128, BATCH * NHEAD, NSPLIT);
    attn_kernel<<<gattn, 128, ATTN_SMEM_BYTES>>>();

    // combine partials -> fp16 ctx
    reduce_kernel<<<(NIN / 4 + 255) / 256, 256>>>();

    // Output projection (fp32 out)
    dim3 gout(D_MODEL / 128, MTOT / 64);
    oproj_kernel<<<gout, 128, GEMM_SMEM_BYTES>>>(out);
}

// round 15
// speedup vs baseline: 1.0979x; 1.0979x over previous
#include <cuda_runtime.h>
#include <cuda_fp16.h>

#define D_MODEL 768
#define SEQ     2048
#define BATCH   2
#define NHEAD   12
#define DK      64
#define MTOT    (BATCH*SEQ)   /* 4096 */
#define NIN     (MTOT*D_MODEL)
#define NW      (D_MODEL*D_MODEL)

// fp16 copies of inputs + intermediates (no cudaMalloc allowed)
__device__ __half g_qin[NIN], g_kin[NIN], g_vin[NIN];
__device__ __half g_wq[NW], g_wk[NW], g_wv[NW], g_wo[NW];
__device__ __half g_Qh[NIN], g_Kh[NIN], g_Vh[NIN], g_ctxh[NIN];

extern __shared__ unsigned char dynsm[];

// ---------------------------------------------------------------------------
// helpers
// ---------------------------------------------------------------------------
__device__ __forceinline__ void mma16(float d[4], const unsigned a[4], const unsigned b[2]) {
    asm volatile(
        "mma.sync.aligned.m16n8k16.row.col.f32.f16.f16.f32 "
        "{%0,%1,%2,%3},{%4,%5,%6,%7},{%8,%9},{%0,%1,%2,%3};"
        : "+f"(d[0]), "+f"(d[1]), "+f"(d[2]), "+f"(d[3])
        : "r"(a[0]), "r"(a[1]), "r"(a[2]), "r"(a[3]),
          "r"(b[0]), "r"(b[1]));
}
__device__ __forceinline__ unsigned ld32(const __half* p) {
    return *(const unsigned*)p;
}
__device__ __forceinline__ unsigned h2u(float x, float y) {
    __half2 h = __floats2half2_rn(x, y);
    return *(unsigned*)&h;
}
__device__ __forceinline__ float ex2(float x) {
    float r;
    asm("ex2.approx.f32 %0, %1;" : "=f"(r) : "f"(x));
    return r;
}
__device__ __forceinline__ void cp16(void* dst, const void* src) {
    unsigned d = (unsigned)__cvta_generic_to_shared(dst);
    asm volatile("cp.async.cg.shared.global [%0], [%1], 16;\n" :: "r"(d), "l"(src));
}
__device__ __forceinline__ void cp_commit() {
    asm volatile("cp.async.commit_group;\n" ::: "memory");
}
template <int N>
__device__ __forceinline__ void cp_wait() {
    asm volatile("cp.async.wait_group %0;\n" :: "n"(N) : "memory");
}
__device__ __forceinline__ void ldm_x4(unsigned& r0, unsigned& r1,
                                       unsigned& r2, unsigned& r3, const __half* p) {
    unsigned a = (unsigned)__cvta_generic_to_shared(p);
    asm volatile("ldmatrix.sync.aligned.m8n8.x4.shared.b16 {%0,%1,%2,%3}, [%4];"
                 : "=r"(r0), "=r"(r1), "=r"(r2), "=r"(r3) : "r"(a));
}
__device__ __forceinline__ void ldm_x4_t(unsigned& r0, unsigned& r1,
                                         unsigned& r2, unsigned& r3, const __half* p) {
    unsigned a = (unsigned)__cvta_generic_to_shared(p);
    asm volatile("ldmatrix.sync.aligned.m8n8.x4.trans.shared.b16 {%0,%1,%2,%3}, [%4];"
                 : "=r"(r0), "=r"(r1), "=r"(r2), "=r"(r3) : "r"(a));
}

#define LOG2E 1.4426950408889634f

// ---------------------------------------------------------------------------
// fp32 -> fp16 conversion pre-pass (7 arrays via blockIdx.y)
// ---------------------------------------------------------------------------
__global__ void __launch_bounds__(256)
cvt_kernel(const float* q, const float* k, const float* v,
           const float* wq, const float* wk, const float* wv, const float* wo)
{
    const int y = blockIdx.y;
    const float* src;
    __half* dst;
    int n;
    switch (y) {
        case 0: src = q;  dst = g_qin; n = NIN; break;
        case 1: src = k;  dst = g_kin; n = NIN; break;
        case 2: src = v;  dst = g_vin; n = NIN; break;
        case 3: src = wq; dst = g_wq;  n = NW;  break;
        case 4: src = wk; dst = g_wk;  n = NW;  break;
        case 5: src = wv; dst = g_wv;  n = NW;  break;
        default: src = wo; dst = g_wo; n = NW;  break;
    }
    int i = (blockIdx.x * 256 + threadIdx.x) * 4;
    if (i >= n) return;
    float4 f = *(const float4*)(src + i);
    __half2* d2 = (__half2*)(dst + i);
    d2[0] = __floats2half2_rn(f.x, f.y);
    d2[1] = __floats2half2_rn(f.z, f.w);
}

// ---------------------------------------------------------------------------
// fp16 GEMM: C[M,N] = A[M,768] @ W[N,768]^T, tile 64x128x64, 128 threads
// (4 warps, warp tile 32x64), occ 4. 2-stage double buffer, ONE barrier
// per K-iteration: cp_wait<0> -> sync -> stage(t+1) -> compute(t).
// Fragments via ldmatrix.x4; row stride 72 halves (conflict-free).
// ---------------------------------------------------------------------------
#define GHP 72
#define GABUF (64 * GHP)                  /* halves per A stage  */
#define GWBUF (128 * GHP)                 /* halves per W stage  */
#define GEMM_SMEM_BYTES (2 * (GABUF + GWBUF) * 2)   /* 55296 B */

__device__ __forceinline__ void gemm_stage(__half* Ad, __half* Wd,
                                           const __half* __restrict__ A,
                                           const __half* __restrict__ W,
                                           int bm, int bn, int k0, int tid)
{
#pragma unroll
    for (int u = 0; u < 4; u++) {         // A: 64 rows x 64 halves
        int idx = tid + (u << 7);
        int r = idx >> 3;
        int c = (idx & 7) << 3;
        cp16(&Ad[r * GHP + c], A + (size_t)(bm + r) * D_MODEL + k0 + c);
    }
#pragma unroll
    for (int u = 0; u < 8; u++) {         // W: 128 rows x 64 halves
        int idx = tid + (u << 7);
        int r = idx >> 3;
        int c = (idx & 7) << 3;
        cp16(&Wd[r * GHP + c], W + (size_t)(bn + r) * D_MODEL + k0 + c);
    }
    cp_commit();
}

__device__ __forceinline__ void gemm_fp16(const __half* __restrict__ A,
                                          const __half* __restrict__ W,
                                          __half* __restrict__ Ch,
                                          float* __restrict__ Cf,
                                          float scale)
{
    __half* As = (__half*)dynsm;                 // 2 x GABUF
    __half* Ws = (__half*)dynsm + 2 * GABUF;     // 2 x GWBUF

    const int tid  = threadIdx.x;
    const int lane = tid & 31;
    const int warp = tid >> 5;
    const int wm   = (warp & 1) * 32;
    const int wn   = (warp >> 1) * 64;
    const int bm   = blockIdx.y * 64;
    const int bn   = blockIdx.x * 128;

    const int a_row = (lane & 15);
    const int a_kof = (lane >> 4) << 3;
    const int b_row = (lane & 7) + ((lane & 16) >> 1);
    const int b_kof = (lane & 8);

    float acc[2][8][4];
#pragma unroll
    for (int mi = 0; mi < 2; mi++)
#pragma unroll
        for (int ni = 0; ni < 8; ni++)
#pragma unroll
            for (int r = 0; r < 4; r++) acc[mi][ni][r] = 0.0f;

    gemm_stage(As, Ws, A, W, bm, bn, 0, tid);

    const int NT = D_MODEL / 64;   // 12
    for (int t = 0; t < NT; t++) {
        cp_wait<0>();              // stage(t) landed (per-thread)
        __syncthreads();           // visibility + buf(t-1) readers done
        if (t + 1 < NT)
            gemm_stage(As + ((t + 1) & 1) * GABUF, Ws + ((t + 1) & 1) * GWBUF,
                       A, W, bm, bn, (t + 1) * 64, tid);

        const __half* Ab = As + (t & 1) * GABUF;
        const __half* Wb = Ws + (t & 1) * GWBUF;

#pragma unroll
        for (int ks = 0; ks < 4; ks++) {
            const int kc = ks << 4;
            unsigned a[2][4], b[8][2];
#pragma unroll
            for (int mi = 0; mi < 2; mi++)
                ldm_x4(a[mi][0], a[mi][1], a[mi][2], a[mi][3],
                       Ab + (wm + (mi << 4) + a_row) * GHP + kc + a_kof);
#pragma unroll
            for (int np = 0; np < 4; np++)
                ldm_x4(b[2 * np][0], b[2 * np][1], b[2 * np + 1][0], b[2 * np + 1][1],
                       Wb + (wn + (np << 4) + b_row) * GHP + kc + b_kof);
#pragma unroll
            for (int mi = 0; mi < 2; mi++)
#pragma unroll
                for (int ni = 0; ni < 8; ni++)
                    mma16(acc[mi][ni], a[mi], b[ni]);
        }
    }

#pragma unroll
    for (int mi = 0; mi < 2; mi++) {
#pragma unroll
        for (int ni = 0; ni < 8; ni++) {
            int row = bm + wm + (mi << 4) + (lane >> 2);
            int col = bn + wn + (ni << 3) + ((lane & 3) << 1);
            if (Ch) {
                *(__half2*)(Ch + (size_t)row * D_MODEL + col) =
                    __floats2half2_rn(acc[mi][ni][0] * scale, acc[mi][ni][1] * scale);
                *(__half2*)(Ch + (size_t)(row + 8) * D_MODEL + col) =
                    __floats2half2_rn(acc[mi][ni][2] * scale, acc[mi][ni][3] * scale);
            } else {
                *(float2*)(Cf + (size_t)row * D_MODEL + col) =
                    make_float2(acc[mi][ni][0], acc[mi][ni][1]);
                *(float2*)(Cf + (size_t)(row + 8) * D_MODEL + col) =
                    make_float2(acc[mi][ni][2], acc[mi][ni][3]);
            }
        }
    }
}

__global__ void __launch_bounds__(128, 4)
qkv_proj_kernel()
{
    const int z = blockIdx.z;
    const __half* A = (z == 0) ? g_qin : (z == 1) ? g_kin : g_vin;
    const __half* W = (z == 0) ? g_wq  : (z == 1) ? g_wk  : g_wv;
    __half*       C = (z == 0) ? g_Qh  : (z == 1) ? g_Kh  : g_Vh;
    float scale = (z == 0) ? 0.125f * LOG2E : 1.0f;
    gemm_fp16(A, W, C, nullptr, scale);
}

__global__ void __launch_bounds__(128, 4)
oproj_kernel(float* __restrict__ out)
{
    gemm_fp16(g_ctxh, g_wo, nullptr, out, 1.0f);
}

// ---------------------------------------------------------------------------
// fp16 flash attention (R13 body, single-sync pipeline): NO-MAX base-2
// softmax, P in registers, l via ones-column MMA, ldmatrix everywhere.
// Pipeline per tile: cp_wait<0> -> sync -> stage(t+1) -> compute(t).
// ---------------------------------------------------------------------------
#define ATP 72
#define KVBUF (64 * ATP)
#define ATTN_SMEM_BYTES (4 * KVBUF * 2)   /* 36864 B */

__device__ __forceinline__ void attn_stage(__half* Kd, __half* Vd,
                                           const __half* __restrict__ Kg,
                                           const __half* __restrict__ Vg,
                                           int kt, int tid)
{
#pragma unroll
    for (int u = 0; u < 4; u++) {
        int idx = tid + (u << 7);
        int r = idx >> 3;
        int c = (idx & 7) << 3;
        cp16(&Kd[r * ATP + c], Kg + (size_t)(kt + r) * D_MODEL + c);
        cp16(&Vd[r * ATP + c], Vg + (size_t)(kt + r) * D_MODEL + c);
    }
    cp_commit();
}

__global__ void __launch_bounds__(128, 2)
attn_kernel()
{
    const int tid  = threadIdx.x;
    const int lane = tid & 31;
    const int warp = tid >> 5;
    const int bh   = blockIdx.y;
    const int b    = bh / NHEAD;
    const int h    = bh % NHEAD;
    const int q0   = blockIdx.x * 128;

    __half* Ks = (__half*)dynsm;
    __half* Vs = Ks + 2 * KVBUF;

    const __half* Qg = g_Qh + (size_t)(b * SEQ + q0) * D_MODEL + h * DK;
    const __half* Kg = g_Kh + (size_t)(b * SEQ) * D_MODEL + h * DK;
    const __half* Vg = g_Vh + (size_t)(b * SEQ) * D_MODEL + h * DK;

    attn_stage(Ks, Vs, Kg, Vg, 0, tid);

    const int wrow = warp << 5;
    unsigned q[2][4][4];
#pragma unroll
    for (int mi = 0; mi < 2; mi++) {
#pragma unroll
        for (int ks = 0; ks < 4; ks++) {
            const __half* qp = Qg + (size_t)(wrow + (mi << 4) + (lane >> 2)) * D_MODEL
                                  + (ks << 4) + ((lane & 3) << 1);
            q[mi][ks][0] = ld32(qp);
            q[mi][ks][1] = ld32(qp + 8 * D_MODEL);
            q[mi][ks][2] = ld32(qp + 8);
            q[mi][ks][3] = ld32(qp + 8 * D_MODEL + 8);
        }
    }

    const unsigned bone = (lane < 4) ? 0x3C003C00u : 0u;
    unsigned b_ones[2] = {bone, bone};

    const int b_row = (lane & 7) + ((lane & 16) >> 1);
    const int b_kof = (lane & 8);

    float o[2][8][4];
    float ol[2][4];
#pragma unroll
    for (int mi = 0; mi < 2; mi++) {
#pragma unroll
        for (int nt = 0; nt < 8; nt++)
#pragma unroll
            for (int r = 0; r < 4; r++) o[mi][nt][r] = 0.0f;
#pragma unroll
        for (int r = 0; r < 4; r++) ol[mi][r] = 0.0f;
    }

    const int NT = SEQ / 64;   // 32

    for (int t = 0; t < NT; t++) {
        cp_wait<0>();
        __syncthreads();
        if (t + 1 < NT)
            attn_stage(Ks + ((t + 1) & 1) * KVBUF, Vs + ((t + 1) & 1) * KVBUF,
                       Kg, Vg, (t + 1) * 64, tid);

        const __half* Kb = Ks + (t & 1) * KVBUF;
        const __half* Vb = Vs + (t & 1) * KVBUF;

        float s[2][8][4];
#pragma unroll
        for (int mi = 0; mi < 2; mi++)
#pragma unroll
            for (int nt = 0; nt < 8; nt++)
#pragma unroll
                for (int r = 0; r < 4; r++) s[mi][nt][r] = 0.0f;

#pragma unroll
        for (int ks = 0; ks < 4; ks++) {
            const int kc = ks << 4;
#pragma unroll
            for (int np = 0; np < 4; np++) {
                unsigned bb[2][2];
                ldm_x4(bb[0][0], bb[0][1], bb[1][0], bb[1][1],
                       Kb + ((np << 4) + b_row) * ATP + kc + b_kof);
                mma16(s[0][2 * np],     q[0][ks], bb[0]);
                mma16(s[1][2 * np],     q[1][ks], bb[0]);
                mma16(s[0][2 * np + 1], q[0][ks], bb[1]);
                mma16(s[1][2 * np + 1], q[1][ks], bb[1]);
            }
        }

#pragma unroll
        for (int mi = 0; mi < 2; mi++)
#pragma unroll
            for (int nt = 0; nt < 8; nt++)
#pragma unroll
                for (int r = 0; r < 4; r++) s[mi][nt][r] = ex2(s[mi][nt][r]);

#pragma unroll
        for (int ks = 0; ks < 4; ks++) {
            unsigned a0[4], a1[4];
            a0[0] = h2u(s[0][2 * ks][0],     s[0][2 * ks][1]);
            a0[1] = h2u(s[0][2 * ks][2],     s[0][2 * ks][3]);
            a0[2] = h2u(s[0][2 * ks + 1][0], s[0][2 * ks + 1][1]);
            a0[3] = h2u(s[0][2 * ks + 1][2], s[0][2 * ks + 1][3]);
            a1[0] = h2u(s[1][2 * ks][0],     s[1][2 * ks][1]);
            a1[1] = h2u(s[1][2 * ks][2],     s[1][2 * ks][3]);
            a1[2] = h2u(s[1][2 * ks + 1][0], s[1][2 * ks + 1][1]);
            a1[3] = h2u(s[1][2 * ks + 1][2], s[1][2 * ks + 1][3]);

            mma16(ol[0], a0, b_ones);
            mma16(ol[1], a1, b_ones);
#pragma unroll
            for (int nt2 = 0; nt2 < 4; nt2++) {
                int row = (ks << 4) + (lane & 15);
                int col = (nt2 << 4) + ((lane & 16) >> 1);
                unsigned r0, r1, r2, r3;
                ldm_x4_t(r0, r1, r2, r3, Vb + row * ATP + col);
                unsigned b0[2] = {r0, r1};
                unsigned b1[2] = {r2, r3};
                mma16(o[0][2 * nt2],     a0, b0);
                mma16(o[1][2 * nt2],     a1, b0);
                mma16(o[0][2 * nt2 + 1], a0, b1);
                mma16(o[1][2 * nt2 + 1], a1, b1);
            }
        }
    }

    __half* Cg = g_ctxh + (size_t)(b * SEQ + q0) * D_MODEL + h * DK;
#pragma unroll
    for (int mi = 0; mi < 2; mi++) {
        int row = wrow + (mi << 4) + (lane >> 2);
        float l0 = __shfl_sync(0xffffffffu, ol[mi][0], lane & 28);
        float l1 = __shfl_sync(0xffffffffu, ol[mi][2], lane & 28);
        float inv0 = 1.0f / l0;
        float inv1 = 1.0f / l1;
#pragma unroll
        for (int nt = 0; nt < 8; nt++) {
            int col = (nt << 3) + ((lane & 3) << 1);
            *(__half2*)(Cg + (size_t)row * D_MODEL + col) =
                __floats2half2_rn(o[mi][nt][0] * inv0, o[mi][nt][1] * inv0);
            *(__half2*)(Cg + (size_t)(row + 8) * D_MODEL + col) =
                __floats2half2_rn(o[mi][nt][2] * inv1, o[mi][nt][3] * inv1);
        }
    }
}

// ---------------------------------------------------------------------------
extern "C" void kernel_launch(void* const* d_in, const int* in_sizes, int n_in,
                              void* d_out, int out_size)
{
    const float* query  = (const float*)d_in[0];
    const float* key_in = (const float*)d_in[1];
    const float* value  = (const float*)d_in[2];
    const float* Wq     = (const float*)d_in[3];
    const float* Wk     = (const float*)d_in[4];
    const float* Wv     = (const float*)d_in[5];
    const float* Wo     = (const float*)d_in[6];
    float* out = (float*)d_out;

    cudaFuncSetAttribute(attn_kernel,
                         cudaFuncAttributeMaxDynamicSharedMemorySize, ATTN_SMEM_BYTES);
    cudaFuncSetAttribute(qkv_proj_kernel,
                         cudaFuncAttributeMaxDynamicSharedMemorySize, GEMM_SMEM_BYTES);
    cudaFuncSetAttribute(oproj_kernel,
                         cudaFuncAttributeMaxDynamicSharedMemorySize, GEMM_SMEM_BYTES);

    // fp32 -> fp16 pre-pass
    dim3 gcvt((NIN / 4 + 255) / 256, 7);
    cvt_kernel<<<gcvt, 256>>>(query, key_in, value, Wq, Wk, Wv, Wo);

    // Q/K/V projections: 64x128 tiles, BK=64, 4 CTA/SM
    dim3 gproj(D_MODEL / 128, MTOT / 64, 3);
    qkv_proj_kernel<<<gproj, 128, GEMM_SMEM_BYTES>>>();

    // Flash attention
    dim3 gattn(SEQ / 128, BATCH * NHEAD);
    attn_kernel<<<gattn, 128, ATTN_SMEM_BYTES>>>();

    // Output projection (fp32 out)
    dim3 gout(D_MODEL / 128, MTOT / 64);
    oproj_kernel<<<gout, 128, GEMM_SMEM_BYTES>>>(out);
}

// round 16
// speedup vs baseline: 1.1272x; 1.0267x over previous
#include <cuda_runtime.h>
#include <cuda_fp16.h>

#define D_MODEL 768
#define SEQ     2048
#define BATCH   2
#define NHEAD   12
#define DK      64
#define MTOT    (BATCH*SEQ)   /* 4096 */
#define NIN     (MTOT*D_MODEL)
#define NW      (D_MODEL*D_MODEL)

// fp16 copies of inputs + intermediates (no cudaMalloc allowed)
__device__ __half g_qin[NIN], g_kin[NIN], g_vin[NIN];
__device__ __half g_wq[NW], g_wk[NW], g_wv[NW], g_wo[NW];
__device__ __half g_Qh[NIN], g_Kh[NIN], g_Vh[NIN], g_ctxh[NIN];

extern __shared__ unsigned char dynsm[];

// ---------------------------------------------------------------------------
// helpers
// ---------------------------------------------------------------------------
__device__ __forceinline__ void mma16(float d[4], const unsigned a[4], const unsigned b[2]) {
    asm volatile(
        "mma.sync.aligned.m16n8k16.row.col.f32.f16.f16.f32 "
        "{%0,%1,%2,%3},{%4,%5,%6,%7},{%8,%9},{%0,%1,%2,%3};"
        : "+f"(d[0]), "+f"(d[1]), "+f"(d[2]), "+f"(d[3])
        : "r"(a[0]), "r"(a[1]), "r"(a[2]), "r"(a[3]),
          "r"(b[0]), "r"(b[1]));
}
__device__ __forceinline__ unsigned ld32(const __half* p) {
    return *(const unsigned*)p;
}
__device__ __forceinline__ unsigned h2u(float x, float y) {
    __half2 h = __floats2half2_rn(x, y);
    return *(unsigned*)&h;
}
__device__ __forceinline__ float ex2(float x) {
    float r;
    asm("ex2.approx.f32 %0, %1;" : "=f"(r) : "f"(x));
    return r;
}
__device__ __forceinline__ void cp16(void* dst, const void* src) {
    unsigned d = (unsigned)__cvta_generic_to_shared(dst);
    asm volatile("cp.async.cg.shared.global [%0], [%1], 16;\n" :: "r"(d), "l"(src));
}
__device__ __forceinline__ void cp_commit() {
    asm volatile("cp.async.commit_group;\n" ::: "memory");
}
template <int N>
__device__ __forceinline__ void cp_wait() {
    asm volatile("cp.async.wait_group %0;\n" :: "n"(N) : "memory");
}
__device__ __forceinline__ void ldm_x4(unsigned& r0, unsigned& r1,
                                       unsigned& r2, unsigned& r3, const __half* p) {
    unsigned a = (unsigned)__cvta_generic_to_shared(p);
    asm volatile("ldmatrix.sync.aligned.m8n8.x4.shared.b16 {%0,%1,%2,%3}, [%4];"
                 : "=r"(r0), "=r"(r1), "=r"(r2), "=r"(r3) : "r"(a));
}
__device__ __forceinline__ void ldm_x4_t(unsigned& r0, unsigned& r1,
                                         unsigned& r2, unsigned& r3, const __half* p) {
    unsigned a = (unsigned)__cvta_generic_to_shared(p);
    asm volatile("ldmatrix.sync.aligned.m8n8.x4.trans.shared.b16 {%0,%1,%2,%3}, [%4];"
                 : "=r"(r0), "=r"(r1), "=r"(r2), "=r"(r3) : "r"(a));
}

#define LOG2E 1.4426950408889634f

// ---------------------------------------------------------------------------
// fp32 -> fp16 conversion pre-pass (7 arrays via blockIdx.y)
// ---------------------------------------------------------------------------
__global__ void __launch_bounds__(256)
cvt_kernel(const float* q, const float* k, const float* v,
           const float* wq, const float* wk, const float* wv, const float* wo)
{
    const int y = blockIdx.y;
    const float* src;
    __half* dst;
    int n;
    switch (y) {
        case 0: src = q;  dst = g_qin; n = NIN; break;
        case 1: src = k;  dst = g_kin; n = NIN; break;
        case 2: src = v;  dst = g_vin; n = NIN; break;
        case 3: src = wq; dst = g_wq;  n = NW;  break;
        case 4: src = wk; dst = g_wk;  n = NW;  break;
        case 5: src = wv; dst = g_wv;  n = NW;  break;
        default: src = wo; dst = g_wo; n = NW;  break;
    }
    int i = (blockIdx.x * 256 + threadIdx.x) * 4;
    if (i >= n) return;
    float4 f = *(const float4*)(src + i);
    __half2* d2 = (__half2*)(dst + i);
    d2[0] = __floats2half2_rn(f.x, f.y);
    d2[1] = __floats2half2_rn(f.z, f.w);
}

// ---------------------------------------------------------------------------
// fp16 GEMM (R15, frozen): tile 64x128x64, 128 threads, occ 4,
// 2-stage single-sync pipeline, ldmatrix fragments.
// ---------------------------------------------------------------------------
#define GHP 72
#define GABUF (64 * GHP)
#define GWBUF (128 * GHP)
#define GEMM_SMEM_BYTES (2 * (GABUF + GWBUF) * 2)   /* 55296 B */

__device__ __forceinline__ void gemm_stage(__half* Ad, __half* Wd,
                                           const __half* __restrict__ A,
                                           const __half* __restrict__ W,
                                           int bm, int bn, int k0, int tid)
{
#pragma unroll
    for (int u = 0; u < 4; u++) {
        int idx = tid + (u << 7);
        int r = idx >> 3;
        int c = (idx & 7) << 3;
        cp16(&Ad[r * GHP + c], A + (size_t)(bm + r) * D_MODEL + k0 + c);
    }
#pragma unroll
    for (int u = 0; u < 8; u++) {
        int idx = tid + (u << 7);
        int r = idx >> 3;
        int c = (idx & 7) << 3;
        cp16(&Wd[r * GHP + c], W + (size_t)(bn + r) * D_MODEL + k0 + c);
    }
    cp_commit();
}

__device__ __forceinline__ void gemm_fp16(const __half* __restrict__ A,
                                          const __half* __restrict__ W,
                                          __half* __restrict__ Ch,
                                          float* __restrict__ Cf,
                                          float scale)
{
    __half* As = (__half*)dynsm;
    __half* Ws = (__half*)dynsm + 2 * GABUF;

    const int tid  = threadIdx.x;
    const int lane = tid & 31;
    const int warp = tid >> 5;
    const int wm   = (warp & 1) * 32;
    const int wn   = (warp >> 1) * 64;
    const int bm   = blockIdx.y * 64;
    const int bn   = blockIdx.x * 128;

    const int a_row = (lane & 15);
    const int a_kof = (lane >> 4) << 3;
    const int b_row = (lane & 7) + ((lane & 16) >> 1);
    const int b_kof = (lane & 8);

    float acc[2][8][4];
#pragma unroll
    for (int mi = 0; mi < 2; mi++)
#pragma unroll
        for (int ni = 0; ni < 8; ni++)
#pragma unroll
            for (int r = 0; r < 4; r++) acc[mi][ni][r] = 0.0f;

    gemm_stage(As, Ws, A, W, bm, bn, 0, tid);

    const int NT = D_MODEL / 64;   // 12
    for (int t = 0; t < NT; t++) {
        cp_wait<0>();
        __syncthreads();
        if (t + 1 < NT)
            gemm_stage(As + ((t + 1) & 1) * GABUF, Ws + ((t + 1) & 1) * GWBUF,
                       A, W, bm, bn, (t + 1) * 64, tid);

        const __half* Ab = As + (t & 1) * GABUF;
        const __half* Wb = Ws + (t & 1) * GWBUF;

#pragma unroll
        for (int ks = 0; ks < 4; ks++) {
            const int kc = ks << 4;
            unsigned a[2][4], b[8][2];
#pragma unroll
            for (int mi = 0; mi < 2; mi++)
                ldm_x4(a[mi][0], a[mi][1], a[mi][2], a[mi][3],
                       Ab + (wm + (mi << 4) + a_row) * GHP + kc + a_kof);
#pragma unroll
            for (int np = 0; np < 4; np++)
                ldm_x4(b[2 * np][0], b[2 * np][1], b[2 * np + 1][0], b[2 * np + 1][1],
                       Wb + (wn + (np << 4) + b_row) * GHP + kc + b_kof);
#pragma unroll
            for (int mi = 0; mi < 2; mi++)
#pragma unroll
                for (int ni = 0; ni < 8; ni++)
                    mma16(acc[mi][ni], a[mi], b[ni]);
        }
    }

#pragma unroll
    for (int mi = 0; mi < 2; mi++) {
#pragma unroll
        for (int ni = 0; ni < 8; ni++) {
            int row = bm + wm + (mi << 4) + (lane >> 2);
            int col = bn + wn + (ni << 3) + ((lane & 3) << 1);
            if (Ch) {
                *(__half2*)(Ch + (size_t)row * D_MODEL + col) =
                    __floats2half2_rn(acc[mi][ni][0] * scale, acc[mi][ni][1] * scale);
                *(__half2*)(Ch + (size_t)(row + 8) * D_MODEL + col) =
                    __floats2half2_rn(acc[mi][ni][2] * scale, acc[mi][ni][3] * scale);
            } else {
                *(float2*)(Cf + (size_t)row * D_MODEL + col) =
                    make_float2(acc[mi][ni][0], acc[mi][ni][1]);
                *(float2*)(Cf + (size_t)(row + 8) * D_MODEL + col) =
                    make_float2(acc[mi][ni][2], acc[mi][ni][3]);
            }
        }
    }
}

__global__ void __launch_bounds__(128, 4)
qkv_proj_kernel()
{
    const int z = blockIdx.z;
    const __half* A = (z == 0) ? g_qin : (z == 1) ? g_kin : g_vin;
    const __half* W = (z == 0) ? g_wq  : (z == 1) ? g_wk  : g_wv;
    __half*       C = (z == 0) ? g_Qh  : (z == 1) ? g_Kh  : g_Vh;
    float scale = (z == 0) ? 0.125f * LOG2E : 1.0f;
    gemm_fp16(A, W, C, nullptr, scale);
}

__global__ void __launch_bounds__(128, 4)
oproj_kernel(float* __restrict__ out)
{
    gemm_fp16(g_ctxh, g_wo, nullptr, out, 1.0f);
}

// ---------------------------------------------------------------------------
// fp16 flash attention, occupancy 3: the 64-key tile is processed as two
// 32-key chunks (S-chunk -> ex2 -> pack -> PV) so the S fragment set
// halves (32 regs), fitting 3 CTAs/SM. Same arithmetic order as before.
// NO-MAX base-2 softmax, P in registers, l via ones-column MMA.
// ---------------------------------------------------------------------------
#define ATP 72
#define KVBUF (64 * ATP)
#define ATTN_SMEM_BYTES (4 * KVBUF * 2)   /* 36864 B */

__device__ __forceinline__ void attn_stage(__half* Kd, __half* Vd,
                                           const __half* __restrict__ Kg,
                                           const __half* __restrict__ Vg,
                                           int kt, int tid)
{
#pragma unroll
    for (int u = 0; u < 4; u++) {
        int idx = tid + (u << 7);
        int r = idx >> 3;
        int c = (idx & 7) << 3;
        cp16(&Kd[r * ATP + c], Kg + (size_t)(kt + r) * D_MODEL + c);
        cp16(&Vd[r * ATP + c], Vg + (size_t)(kt + r) * D_MODEL + c);
    }
    cp_commit();
}

__global__ void __launch_bounds__(128, 3)
attn_kernel()
{
    const int tid  = threadIdx.x;
    const int lane = tid & 31;
    const int warp = tid >> 5;
    const int bh   = blockIdx.y;
    const int b    = bh / NHEAD;
    const int h    = bh % NHEAD;
    const int q0   = blockIdx.x * 128;

    __half* Ks = (__half*)dynsm;
    __half* Vs = Ks + 2 * KVBUF;

    const __half* Qg = g_Qh + (size_t)(b * SEQ + q0) * D_MODEL + h * DK;
    const __half* Kg = g_Kh + (size_t)(b * SEQ) * D_MODEL + h * DK;
    const __half* Vg = g_Vh + (size_t)(b * SEQ) * D_MODEL + h * DK;

    attn_stage(Ks, Vs, Kg, Vg, 0, tid);

    const int wrow = warp << 5;
    unsigned q[2][4][4];
#pragma unroll
    for (int mi = 0; mi < 2; mi++) {
#pragma unroll
        for (int ks = 0; ks < 4; ks++) {
            const __half* qp = Qg + (size_t)(wrow + (mi << 4) + (lane >> 2)) * D_MODEL
                                  + (ks << 4) + ((lane & 3) << 1);
            q[mi][ks][0] = ld32(qp);
            q[mi][ks][1] = ld32(qp + 8 * D_MODEL);
            q[mi][ks][2] = ld32(qp + 8);
            q[mi][ks][3] = ld32(qp + 8 * D_MODEL + 8);
        }
    }

    const unsigned bone = (lane < 4) ? 0x3C003C00u : 0u;
    unsigned b_ones[2] = {bone, bone};

    const int b_row = (lane & 7) + ((lane & 16) >> 1);
    const int b_kof = (lane & 8);

    float o[2][8][4];
    float ol[2][4];
#pragma unroll
    for (int mi = 0; mi < 2; mi++) {
#pragma unroll
        for (int nt = 0; nt < 8; nt++)
#pragma unroll
            for (int r = 0; r < 4; r++) o[mi][nt][r] = 0.0f;
#pragma unroll
        for (int r = 0; r < 4; r++) ol[mi][r] = 0.0f;
    }

    const int NT = SEQ / 64;   // 32

    for (int t = 0; t < NT; t++) {
        cp_wait<0>();
        __syncthreads();
        if (t + 1 < NT)
            attn_stage(Ks + ((t + 1) & 1) * KVBUF, Vs + ((t + 1) & 1) * KVBUF,
                       Kg, Vg, (t + 1) * 64, tid);

        const __half* Kb = Ks + (t & 1) * KVBUF;
        const __half* Vb = Vs + (t & 1) * KVBUF;

        // Two 32-key chunks per tile: S-chunk -> ex2 -> pack -> PV-chunk.
#pragma unroll
        for (int kch = 0; kch < 2; kch++) {
            float s[2][4][4];
#pragma unroll
            for (int mi = 0; mi < 2; mi++)
#pragma unroll
                for (int nt = 0; nt < 4; nt++)
#pragma unroll
                    for (int r = 0; r < 4; r++) s[mi][nt][r] = 0.0f;

            // S = Q K^T for keys [32*kch, 32*kch+32)
#pragma unroll
            for (int ks = 0; ks < 4; ks++) {
                const int kc = ks << 4;
#pragma unroll
                for (int np = 0; np < 2; np++) {
                    unsigned bb[2][2];
                    ldm_x4(bb[0][0], bb[0][1], bb[1][0], bb[1][1],
                           Kb + ((kch << 5) + (np << 4) + b_row) * ATP + kc + b_kof);
                    mma16(s[0][2 * np],     q[0][ks], bb[0]);
                    mma16(s[1][2 * np],     q[1][ks], bb[0]);
                    mma16(s[0][2 * np + 1], q[0][ks], bb[1]);
                    mma16(s[1][2 * np + 1], q[1][ks], bb[1]);
                }
            }

            // p = 2^s
#pragma unroll
            for (int mi = 0; mi < 2; mi++)
#pragma unroll
                for (int nt = 0; nt < 4; nt++)
#pragma unroll
                    for (int r = 0; r < 4; r++) s[mi][nt][r] = ex2(s[mi][nt][r]);

            // O += P V ; l += P 1   (PV k-steps 2*kch, 2*kch+1)
#pragma unroll
            for (int kp = 0; kp < 2; kp++) {
                unsigned a0[4], a1[4];
                a0[0] = h2u(s[0][2 * kp][0],     s[0][2 * kp][1]);
                a0[1] = h2u(s[0][2 * kp][2],     s[0][2 * kp][3]);
                a0[2] = h2u(s[0][2 * kp + 1][0], s[0][2 * kp + 1][1]);
                a0[3] = h2u(s[0][2 * kp + 1][2], s[0][2 * kp + 1][3]);
                a1[0] = h2u(s[1][2 * kp][0],     s[1][2 * kp][1]);
                a1[1] = h2u(s[1][2 * kp][2],     s[1][2 * kp][3]);
                a1[2] = h2u(s[1][2 * kp + 1][0], s[1][2 * kp + 1][1]);
                a1[3] = h2u(s[1][2 * kp + 1][2], s[1][2 * kp + 1][3]);

                mma16(ol[0], a0, b_ones);
                mma16(ol[1], a1, b_ones);

                const int vrow = (kch << 5) + (kp << 4) + (lane & 15);
#pragma unroll
                for (int nt2 = 0; nt2 < 4; nt2++) {
                    int col = (nt2 << 4) + ((lane & 16) >> 1);
                    unsigned r0, r1, r2, r3;
                    ldm_x4_t(r0, r1, r2, r3, Vb + vrow * ATP + col);
                    unsigned b0[2] = {r0, r1};
                    unsigned b1[2] = {r2, r3};
                    mma16(o[0][2 * nt2],     a0, b0);
                    mma16(o[1][2 * nt2],     a1, b0);
                    mma16(o[0][2 * nt2 + 1], a0, b1);
                    mma16(o[1][2 * nt2 + 1], a1, b1);
                }
            }
        }
    }

    __half* Cg = g_ctxh + (size_t)(b * SEQ + q0) * D_MODEL + h * DK;
#pragma unroll
    for (int mi = 0; mi < 2; mi++) {
        int row = wrow + (mi << 4) + (lane >> 2);
        float l0 = __shfl_sync(0xffffffffu, ol[mi][0], lane & 28);
        float l1 = __shfl_sync(0xffffffffu, ol[mi][2], lane & 28);
        float inv0 = 1.0f / l0;
        float inv1 = 1.0f / l1;
#pragma unroll
        for (int nt = 0; nt < 8; nt++) {
            int col = (nt << 3) + ((lane & 3) << 1);
            *(__half2*)(Cg + (size_t)row * D_MODEL + col) =
                __floats2half2_rn(o[mi][nt][0] * inv0, o[mi][nt][1] * inv0);
            *(__half2*)(Cg + (size_t)(row + 8) * D_MODEL + col) =
                __floats2half2_rn(o[mi][nt][2] * inv1, o[mi][nt][3] * inv1);
        }
    }
}

// ---------------------------------------------------------------------------
extern "C" void kernel_launch(void* const* d_in, const int* in_sizes, int n_in,
                              void* d_out, int out_size)
{
    const float* query  = (const float*)d_in[0];
    const float* key_in = (const float*)d_in[1];
    const float* value  = (const float*)d_in[2];
    const float* Wq     = (const float*)d_in[3];
    const float* Wk     = (const float*)d_in[4];
    const float* Wv     = (const float*)d_in[5];
    const float* Wo     = (const float*)d_in[6];
    float* out = (float*)d_out;

    cudaFuncSetAttribute(attn_kernel,
                         cudaFuncAttributeMaxDynamicSharedMemorySize, ATTN_SMEM_BYTES);
    cudaFuncSetAttribute(qkv_proj_kernel,
                         cudaFuncAttributeMaxDynamicSharedMemorySize, GEMM_SMEM_BYTES);
    cudaFuncSetAttribute(oproj_kernel,
                         cudaFuncAttributeMaxDynamicSharedMemorySize, GEMM_SMEM_BYTES);

    // fp32 -> fp16 pre-pass
    dim3 gcvt((NIN / 4 + 255) / 256, 7);
    cvt_kernel<<<gcvt, 256>>>(query, key_in, value, Wq, Wk, Wv, Wo);

    // Q/K/V projections: 64x128 tiles, BK=64, 4 CTA/SM
    dim3 gproj(D_MODEL / 128, MTOT / 64, 3);
    qkv_proj_kernel<<<gproj, 128, GEMM_SMEM_BYTES>>>();

    // Flash attention (occupancy 3)
    dim3 gattn(SEQ / 128, BATCH * NHEAD);
    attn_kernel<<<gattn, 128, ATTN_SMEM_BYTES>>>();

    // Output projection (fp32 out)
    dim3 gout(D_MODEL / 128, MTOT / 64);
    oproj_kernel<<<gout, 128, GEMM_SMEM_BYTES>>>(out);
}